// round 1
// baseline (speedup 1.0000x reference)
#include <cuda_runtime.h>
#include <math.h>

// Problem constants
// B=4096, LAT=64, FRAME=512, HID=1024, E=8, GH=128
// IN1 = 576 (z|c), IN2 = 1088 (z|h), OUT = 512

#define NB 4096

// Scratch (device globals -- no allocation allowed)
__device__ float g_coef[NB * 8];
__device__ float g_h0[NB * 1024];
__device__ float g_h1[NB * 1024];

__device__ __forceinline__ float elu1(float x) {
    return x > 0.f ? x : expm1f(x);
}

// ---------------------------------------------------------------------------
// Gate MLP: x0=[z|c] -> elu(fc 576->128) -> elu(fc 128->128) -> softmax(fc 128->8)
// 8 rows per block, 128 threads: thread t owns hidden column t.
// ---------------------------------------------------------------------------
__global__ __launch_bounds__(128) void gate_kernel(
    const float* __restrict__ z, const float* __restrict__ c,
    const float* __restrict__ gw1, const float* __restrict__ gb1,
    const float* __restrict__ gw2, const float* __restrict__ gb2,
    const float* __restrict__ gw3, const float* __restrict__ gb3,
    float* __restrict__ coef)
{
    constexpr int R = 8;
    __shared__ float xs[R][576];
    __shared__ float h1s[R][128];
    __shared__ float h2s[R][128];
    __shared__ float lg[R][8];

    const int tid = threadIdx.x;
    const int b0 = blockIdx.x * R;

    for (int idx = tid; idx < R * 576; idx += 128) {
        int r = idx / 576;
        int i = idx - r * 576;
        xs[r][i] = (i < 64) ? z[(b0 + r) * 64 + i] : c[(b0 + r) * 512 + (i - 64)];
    }
    __syncthreads();

    float acc[R];
    // layer 1: 576 -> 128
    {
        float bv = gb1[tid];
#pragma unroll
        for (int r = 0; r < R; r++) acc[r] = bv;
        for (int i = 0; i < 576; i++) {
            float w = gw1[i * 128 + tid];
#pragma unroll
            for (int r = 0; r < R; r++) acc[r] = fmaf(xs[r][i], w, acc[r]);
        }
#pragma unroll
        for (int r = 0; r < R; r++) h1s[r][tid] = elu1(acc[r]);
    }
    __syncthreads();

    // layer 2: 128 -> 128
    {
        float bv = gb2[tid];
#pragma unroll
        for (int r = 0; r < R; r++) acc[r] = bv;
        for (int i = 0; i < 128; i++) {
            float w = gw2[i * 128 + tid];
#pragma unroll
            for (int r = 0; r < R; r++) acc[r] = fmaf(h1s[r][i], w, acc[r]);
        }
#pragma unroll
        for (int r = 0; r < R; r++) h2s[r][tid] = elu1(acc[r]);
    }
    __syncthreads();

    // layer 3: 128 -> 8 logits (64 active threads: (row, expert))
    if (tid < 64) {
        int r = tid >> 3, e = tid & 7;
        float s = gb3[e];
        for (int i = 0; i < 128; i++) s = fmaf(h2s[r][i], gw3[i * 8 + e], s);
        lg[r][e] = s;
    }
    __syncthreads();

    if (tid < 64) {
        int r = tid >> 3, e = tid & 7;
        float mx = lg[r][0];
#pragma unroll
        for (int j = 1; j < 8; j++) mx = fmaxf(mx, lg[r][j]);
        float sum = 0.f;
#pragma unroll
        for (int j = 0; j < 8; j++) sum += expf(lg[r][j] - mx);
        coef[(b0 + r) * 8 + e] = expf(lg[r][e] - mx) / sum;
    }
}

// ---------------------------------------------------------------------------
// Mixed layer as one dense GEMM:
//   out[b,o] = act( sum_k A'[b,k] * W[k,o] + sum_e coef[b,e]*bias[e,o] )
//   A'[b, e*IN + i] = coef[b,e] * x[b,i],  x = [z (64) | xp (XC)]
// W is the flattened [E*IN, N] row-major expert weight (native layout of w[E,IN,N]).
// BM=128, BK=8, 256 threads, TMxTN thread tile, double-buffered smem.
// IN % 8 == 0 and 64 % 8 == 0 -> each BK tile stays inside one expert and on
// one side of the z/xp concat boundary; all global loads are float4.
// ---------------------------------------------------------------------------
template <int XC, int N, int BN, int TM, int TN, bool ELU>
__global__ __launch_bounds__(256, 2) void mixed_layer_kernel(
    const float* __restrict__ z,
    const float* __restrict__ xp,
    const float* __restrict__ W,
    const float* __restrict__ bias,
    const float* __restrict__ coef,
    float* __restrict__ out)
{
    constexpr int BM = 128;
    constexpr int BK = 8;
    constexpr int IN = 64 + XC;
    constexpr int K = 8 * IN;
    constexpr int NT = K / BK;
    constexpr int TX = BN / TN;        // threads along n
    constexpr int NVB = BK * BN / 4;   // float4s per B tile (<=256)

    __shared__ float As[2][BK][BM];
    __shared__ float Bs[2][BK][BN];
    __shared__ float coefS[BM][9];     // pad to 9 to break bank conflicts
    __shared__ float biasS[8][BN];

    const int tid = threadIdx.x;
    const int m0 = blockIdx.y * BM;
    const int n0 = blockIdx.x * BN;

    for (int idx = tid; idx < BM * 8; idx += 256)
        coefS[idx >> 3][idx & 7] = coef[(m0 + (idx >> 3)) * 8 + (idx & 7)];
    for (int idx = tid; idx < 8 * BN; idx += 256) {
        int e = idx / BN, col = idx - e * BN;
        biasS[e][col] = bias[e * N + n0 + col];
    }
    __syncthreads();   // coefS needed by A-tile fetch

    // A tile: exactly 256 float4s (BM*BK/4) -> one per thread
    const int arow = tid >> 1;
    const int acol = (tid & 1) * 4;
    // B tile mapping
    const int brow = tid / (BN / 4);
    const int bcol = (tid % (BN / 4)) * 4;
    const bool bAct = (tid < NVB);

    auto fetchA = [&](int kt, float4& ra, float& cf) {
        int k = kt * BK + acol;
        int e = k / IN;
        int i = k - e * IN;
        cf = coefS[arow][e];
        int b = m0 + arow;
        if (i < 64) ra = *(const float4*)(z + b * 64 + i);
        else        ra = *(const float4*)(xp + b * XC + (i - 64));
    };
    auto fetchB = [&](int kt, float4& rb) {
        if (bAct) rb = *(const float4*)(W + (kt * BK + brow) * N + n0 + bcol);
    };
    auto storeA = [&](int buf, const float4& ra, float cf) {
        As[buf][acol + 0][arow] = ra.x * cf;
        As[buf][acol + 1][arow] = ra.y * cf;
        As[buf][acol + 2][arow] = ra.z * cf;
        As[buf][acol + 3][arow] = ra.w * cf;
    };
    auto storeB = [&](int buf, const float4& rb) {
        if (bAct) *(float4*)&Bs[buf][brow][bcol] = rb;
    };

    {
        float4 ra, rb; float cf;
        fetchA(0, ra, cf); fetchB(0, rb);
        storeA(0, ra, cf); storeB(0, rb);
    }
    __syncthreads();

    const int tx = tid % TX;
    const int ty = tid / TX;

    float acc[TM][TN];
#pragma unroll
    for (int m = 0; m < TM; m++)
#pragma unroll
        for (int n = 0; n < TN; n++) acc[m][n] = 0.f;

    int buf = 0;
    for (int kt = 0; kt < NT; kt++) {
        float4 ra, rb; float cf;
        const bool more = (kt + 1 < NT);
        if (more) { fetchA(kt + 1, ra, cf); fetchB(kt + 1, rb); }

#pragma unroll
        for (int kk = 0; kk < BK; kk++) {
            float a[TM], bb[TN];
#pragma unroll
            for (int m = 0; m < TM; m += 4)
                *(float4*)&a[m] = *(const float4*)&As[buf][kk][ty * TM + m];
#pragma unroll
            for (int n = 0; n < TN; n += 4)
                *(float4*)&bb[n] = *(const float4*)&Bs[buf][kk][tx * TN + n];
#pragma unroll
            for (int m = 0; m < TM; m++)
#pragma unroll
                for (int n = 0; n < TN; n++)
                    acc[m][n] = fmaf(a[m], bb[n], acc[m][n]);
        }

        if (more) { storeA(buf ^ 1, ra, cf); storeB(buf ^ 1, rb); }
        __syncthreads();
        buf ^= 1;
    }

    // epilogue: + coef·bias, activation, store
#pragma unroll
    for (int m = 0; m < TM; m++) {
        const int row = m0 + ty * TM + m;
        float cvec[8];
#pragma unroll
        for (int e = 0; e < 8; e++) cvec[e] = coefS[ty * TM + m][e];
#pragma unroll
        for (int n = 0; n < TN; n++) {
            float v = acc[m][n];
#pragma unroll
            for (int e = 0; e < 8; e++) v = fmaf(cvec[e], biasS[e][tx * TN + n], v);
            if (ELU) v = elu1(v);
            acc[m][n] = v;
        }
#pragma unroll
        for (int n = 0; n < TN; n += 4)
            *(float4*)(out + row * N + n0 + tx * TN + n) = *(float4*)&acc[m][n];
    }
}

// ---------------------------------------------------------------------------
// Launch: gate -> layer0 (z|c -> 1024, elu) -> layer1 (z|h0 -> 1024, elu)
//              -> layer2 (z|h1 -> 512)
// ---------------------------------------------------------------------------
extern "C" void kernel_launch(void* const* d_in, const int* in_sizes, int n_in,
                              void* d_out, int out_size)
{
    const float* z   = (const float*)d_in[0];
    const float* c   = (const float*)d_in[1];
    const float* w0  = (const float*)d_in[2];
    const float* b0  = (const float*)d_in[3];
    const float* w1  = (const float*)d_in[4];
    const float* b1  = (const float*)d_in[5];
    const float* w2  = (const float*)d_in[6];
    const float* b2  = (const float*)d_in[7];
    const float* gw1 = (const float*)d_in[8];
    const float* gb1 = (const float*)d_in[9];
    const float* gw2 = (const float*)d_in[10];
    const float* gb2 = (const float*)d_in[11];
    const float* gw3 = (const float*)d_in[12];
    const float* gb3 = (const float*)d_in[13];

    float *coef, *h0, *h1;
    cudaGetSymbolAddress((void**)&coef, g_coef);
    cudaGetSymbolAddress((void**)&h0, g_h0);
    cudaGetSymbolAddress((void**)&h1, g_h1);

    gate_kernel<<<NB / 8, 128>>>(z, c, gw1, gb1, gw2, gb2, gw3, gb3, coef);

    // layer0: M=4096, K=8*576=4608, N=1024
    mixed_layer_kernel<512, 1024, 128, 8, 8, true>
        <<<dim3(1024 / 128, NB / 128), 256>>>(z, c, w0, b0, coef, h0);

    // layer1: M=4096, K=8*1088=8704, N=1024
    mixed_layer_kernel<1024, 1024, 128, 8, 8, true>
        <<<dim3(1024 / 128, NB / 128), 256>>>(z, h0, w1, b1, coef, h1);

    // layer2: M=4096, K=8704, N=512 (BN=64 so grid stays at 256 blocks)
    mixed_layer_kernel<1024, 512, 64, 8, 4, false>
        <<<dim3(512 / 64, NB / 128), 256>>>(z, h1, w2, b2, coef, (float*)d_out);
}

// round 2
// speedup vs baseline: 3.4238x; 3.4238x over previous
#include <cuda_runtime.h>
#include <math.h>
#include <stdint.h>

#define NB 4096

// Scratch (device globals -- no allocation allowed)
__device__ float g_coef[NB * 8];
__device__ float g_h0[NB * 1024];
__device__ float g_h1[NB * 1024];

__device__ __forceinline__ float elu1(float x) {
    return x > 0.f ? x : expm1f(x);
}

// Round-to-nearest fp32 -> tf32 (RNA is essential: truncation biases the dot
// product by ~2^-10 systematically; RNA errors cancel over K).
__device__ __forceinline__ uint32_t f2tf(float x) {
    uint32_t r;
    asm("cvt.rna.tf32.f32 %0, %1;" : "=r"(r) : "f"(x));
    return r;
}

__device__ __forceinline__ void cp16(uint32_t smem_addr, const void* gptr) {
    asm volatile("cp.async.cg.shared.global [%0], [%1], 16;\n"
                 :: "r"(smem_addr), "l"(gptr));
}
__device__ __forceinline__ void cp_commit() {
    asm volatile("cp.async.commit_group;\n" ::);
}
__device__ __forceinline__ void cp_wait1() {
    asm volatile("cp.async.wait_group 1;\n" ::);
}

__device__ __forceinline__ void mma_tf32(float& d0, float& d1, float& d2, float& d3,
                                         uint32_t a0, uint32_t a1, uint32_t a2, uint32_t a3,
                                         uint32_t b0, uint32_t b1) {
    asm volatile(
        "mma.sync.aligned.m16n8k8.row.col.f32.tf32.tf32.f32 "
        "{%0,%1,%2,%3}, {%4,%5,%6,%7}, {%8,%9}, {%0,%1,%2,%3};\n"
        : "+f"(d0), "+f"(d1), "+f"(d2), "+f"(d3)
        : "r"(a0), "r"(a1), "r"(a2), "r"(a3), "r"(b0), "r"(b1));
}

// ---------------------------------------------------------------------------
// Gate MLP (unchanged): x0=[z|c] -> elu(576->128) -> elu(128->128) -> softmax(128->8)
// ---------------------------------------------------------------------------
__global__ __launch_bounds__(128) void gate_kernel(
    const float* __restrict__ z, const float* __restrict__ c,
    const float* __restrict__ gw1, const float* __restrict__ gb1,
    const float* __restrict__ gw2, const float* __restrict__ gb2,
    const float* __restrict__ gw3, const float* __restrict__ gb3,
    float* __restrict__ coef)
{
    constexpr int R = 8;
    __shared__ float xs[R][576];
    __shared__ float h1s[R][128];
    __shared__ float h2s[R][128];
    __shared__ float lg[R][8];

    const int tid = threadIdx.x;
    const int b0 = blockIdx.x * R;

    for (int idx = tid; idx < R * 576; idx += 128) {
        int r = idx / 576;
        int i = idx - r * 576;
        xs[r][i] = (i < 64) ? z[(b0 + r) * 64 + i] : c[(b0 + r) * 512 + (i - 64)];
    }
    __syncthreads();

    float acc[R];
    {
        float bv = gb1[tid];
#pragma unroll
        for (int r = 0; r < R; r++) acc[r] = bv;
        for (int i = 0; i < 576; i++) {
            float w = gw1[i * 128 + tid];
#pragma unroll
            for (int r = 0; r < R; r++) acc[r] = fmaf(xs[r][i], w, acc[r]);
        }
#pragma unroll
        for (int r = 0; r < R; r++) h1s[r][tid] = elu1(acc[r]);
    }
    __syncthreads();

    {
        float bv = gb2[tid];
#pragma unroll
        for (int r = 0; r < R; r++) acc[r] = bv;
        for (int i = 0; i < 128; i++) {
            float w = gw2[i * 128 + tid];
#pragma unroll
            for (int r = 0; r < R; r++) acc[r] = fmaf(h1s[r][i], w, acc[r]);
        }
#pragma unroll
        for (int r = 0; r < R; r++) h2s[r][tid] = elu1(acc[r]);
    }
    __syncthreads();

    if (tid < 64) {
        int r = tid >> 3, e = tid & 7;
        float s = gb3[e];
        for (int i = 0; i < 128; i++) s = fmaf(h2s[r][i], gw3[i * 8 + e], s);
        lg[r][e] = s;
    }
    __syncthreads();

    if (tid < 64) {
        int r = tid >> 3, e = tid & 7;
        float mx = lg[r][0];
#pragma unroll
        for (int j = 1; j < 8; j++) mx = fmaxf(mx, lg[r][j]);
        float sum = 0.f;
#pragma unroll
        for (int j = 0; j < 8; j++) sum += expf(lg[r][j] - mx);
        coef[(b0 + r) * 8 + e] = expf(lg[r][e] - mx) / sum;
    }
}

// ---------------------------------------------------------------------------
// Mixed layer as dense tf32 tensor-core GEMM.
//   out[b,o] = act( sum_k coef[b,e(k)]*x[b,i(k)] * W[k,o] + sum_e coef[b,e]*bias[e,o] )
// A (x-tiles) staged raw via cp.async; coef scale + tf32 cvt at fragment load
// (valid since BK=32 | IN and BK | 64, so each K-tile has one expert & source).
// Block 128xBN, 8 warps (4m x 2n), warp tile 32 x BN/2, mma m16n8k8.
// ---------------------------------------------------------------------------
template <int XC, int N, int BN, bool ELU>
__global__ __launch_bounds__(256, 2) void mixed_tc_kernel(
    const float* __restrict__ z,
    const float* __restrict__ xp,
    const float* __restrict__ W,
    const float* __restrict__ bias,
    const float* __restrict__ coef,
    float* __restrict__ out)
{
    constexpr int BM = 128;
    constexpr int BK = 32;
    constexpr int IN = 64 + XC;
    constexpr int K = 8 * IN;
    constexpr int NT = K / BK;
    constexpr int AST = BK + 4;   // As stride: bank-bijective fragment loads
    constexpr int BST = BN + 8;   // Bs stride: bank-bijective fragment loads
    constexpr int WN = BN / 2;    // warp n extent
    constexpr int NTN = WN / 8;   // n-direction mma tiles per warp

    extern __shared__ float sm[];
    float* As = sm;                           // 2 stages * BM * AST
    float* Bs = As + 2 * BM * AST;            // 2 stages * BK * BST
    float* coefS = Bs + 2 * BK * BST;         // BM * 9 (padded)
    float* biasS = coefS + BM * 9;            // 8 * BN

    const int tid = threadIdx.x;
    const int m0 = blockIdx.y * BM;
    const int n0 = blockIdx.x * BN;
    const int w = tid >> 5, lane = tid & 31;
    const int wm0 = (w & 3) * 32;
    const int wn0 = (w >> 2) * WN;
    const int g8 = lane >> 2;   // 0..7
    const int t4 = lane & 3;    // 0..3

    auto loadA = [&](int kt, int stg) {
        const int e = (kt * BK) / IN;
        const int i0 = kt * BK - e * IN;
        float* dst = As + stg * BM * AST;
        const float* base;
        int stride;
        if (i0 < 64) { base = z + (size_t)m0 * 64 + i0; stride = 64; }
        else         { base = xp + (size_t)m0 * XC + (i0 - 64); stride = XC; }
#pragma unroll
        for (int j = 0; j < 4; j++) {
            int idx = j * 256 + tid;
            int row = idx >> 3;
            int kc4 = (idx & 7) * 4;
            uint32_t sa = (uint32_t)__cvta_generic_to_shared(dst + row * AST + kc4);
            cp16(sa, base + (size_t)row * stride + kc4);
        }
    };
    auto loadB = [&](int kt, int stg) {
        float* dst = Bs + stg * BK * BST;
        constexpr int NR4 = BN / 4;
        constexpr int PT = (BK * NR4) / 256;
#pragma unroll
        for (int j = 0; j < PT; j++) {
            int idx = j * 256 + tid;
            int kr = idx / NR4;
            int nc4 = (idx - kr * NR4) * 4;
            uint32_t sa = (uint32_t)__cvta_generic_to_shared(dst + kr * BST + nc4);
            cp16(sa, W + (size_t)(kt * BK + kr) * N + n0 + nc4);
        }
    };

    // prologue: stage 0 in flight, then coef/bias via regular path
    loadA(0, 0);
    loadB(0, 0);
    cp_commit();

    for (int idx = tid; idx < BM * 8; idx += 256)
        coefS[(idx >> 3) * 9 + (idx & 7)] = coef[(size_t)(m0 + (idx >> 3)) * 8 + (idx & 7)];
    for (int idx = tid; idx < 8 * BN; idx += 256) {
        int e = idx / BN, cn = idx - e * BN;
        biasS[e * BN + cn] = bias[(size_t)e * N + n0 + cn];
    }

    float acc[2][NTN][4];
#pragma unroll
    for (int mt = 0; mt < 2; mt++)
#pragma unroll
        for (int nt = 0; nt < NTN; nt++)
#pragma unroll
            for (int q = 0; q < 4; q++) acc[mt][nt][q] = 0.f;

    int buf = 0;
    for (int kt = 0; kt < NT; kt++) {
        if (kt + 1 < NT) { loadA(kt + 1, buf ^ 1); loadB(kt + 1, buf ^ 1); }
        cp_commit();
        cp_wait1();
        __syncthreads();

        const int e = (kt * BK) / IN;
        float cf[4];
#pragma unroll
        for (int q = 0; q < 4; q++)
            cf[q] = coefS[(wm0 + g8 + q * 8) * 9 + e];

        const float* Ab = As + buf * BM * AST;
        const float* Bb = Bs + buf * BK * BST;

#pragma unroll
        for (int s = 0; s < 4; s++) {
            uint32_t af[2][4];
#pragma unroll
            for (int mt = 0; mt < 2; mt++) {
                const int r0 = wm0 + mt * 16 + g8;
                af[mt][0] = f2tf(Ab[r0 * AST + s * 8 + t4] * cf[mt * 2 + 0]);
                af[mt][1] = f2tf(Ab[(r0 + 8) * AST + s * 8 + t4] * cf[mt * 2 + 1]);
                af[mt][2] = f2tf(Ab[r0 * AST + s * 8 + t4 + 4] * cf[mt * 2 + 0]);
                af[mt][3] = f2tf(Ab[(r0 + 8) * AST + s * 8 + t4 + 4] * cf[mt * 2 + 1]);
            }
#pragma unroll
            for (int nt = 0; nt < NTN; nt++) {
                const int cn = wn0 + nt * 8 + g8;
                uint32_t b0 = f2tf(Bb[(s * 8 + t4) * BST + cn]);
                uint32_t b1 = f2tf(Bb[(s * 8 + t4 + 4) * BST + cn]);
#pragma unroll
                for (int mt = 0; mt < 2; mt++)
                    mma_tf32(acc[mt][nt][0], acc[mt][nt][1], acc[mt][nt][2], acc[mt][nt][3],
                             af[mt][0], af[mt][1], af[mt][2], af[mt][3], b0, b1);
            }
        }
        __syncthreads();   // protect buf^1 (written next iter) from laggards
        buf ^= 1;
    }

    // epilogue: + coef·bias, activation, store (float2 per c-pair)
#pragma unroll
    for (int mt = 0; mt < 2; mt++) {
#pragma unroll
        for (int half = 0; half < 2; half++) {
            const int rl = wm0 + mt * 16 + g8 + half * 8;
            float cfr[8];
#pragma unroll
            for (int e2 = 0; e2 < 8; e2++) cfr[e2] = coefS[rl * 9 + e2];
            float* orow = out + (size_t)(m0 + rl) * N + n0;
#pragma unroll
            for (int nt = 0; nt < NTN; nt++) {
                const int cl = wn0 + nt * 8 + t4 * 2;
                float v0 = acc[mt][nt][half * 2 + 0];
                float v1 = acc[mt][nt][half * 2 + 1];
#pragma unroll
                for (int e2 = 0; e2 < 8; e2++) {
                    v0 = fmaf(cfr[e2], biasS[e2 * BN + cl], v0);
                    v1 = fmaf(cfr[e2], biasS[e2 * BN + cl + 1], v1);
                }
                if (ELU) { v0 = elu1(v0); v1 = elu1(v1); }
                *(float2*)(orow + cl) = make_float2(v0, v1);
            }
        }
    }
}

// ---------------------------------------------------------------------------

static constexpr int smem_bytes(int BN) {
    return (2 * 128 * 36 + 2 * 32 * (BN + 8) + 128 * 9 + 8 * BN) * 4;
}

extern "C" void kernel_launch(void* const* d_in, const int* in_sizes, int n_in,
                              void* d_out, int out_size)
{
    const float* z   = (const float*)d_in[0];
    const float* c   = (const float*)d_in[1];
    const float* w0  = (const float*)d_in[2];
    const float* b0  = (const float*)d_in[3];
    const float* w1  = (const float*)d_in[4];
    const float* b1  = (const float*)d_in[5];
    const float* w2  = (const float*)d_in[6];
    const float* b2  = (const float*)d_in[7];
    const float* gw1 = (const float*)d_in[8];
    const float* gb1 = (const float*)d_in[9];
    const float* gw2 = (const float*)d_in[10];
    const float* gb2 = (const float*)d_in[11];
    const float* gw3 = (const float*)d_in[12];
    const float* gb3 = (const float*)d_in[13];

    float *coef, *h0, *h1;
    cudaGetSymbolAddress((void**)&coef, g_coef);
    cudaGetSymbolAddress((void**)&h0, g_h0);
    cudaGetSymbolAddress((void**)&h1, g_h1);

    cudaFuncSetAttribute(mixed_tc_kernel<512, 1024, 128, true>,
                         cudaFuncAttributeMaxDynamicSharedMemorySize, smem_bytes(128));
    cudaFuncSetAttribute(mixed_tc_kernel<1024, 1024, 128, true>,
                         cudaFuncAttributeMaxDynamicSharedMemorySize, smem_bytes(128));
    cudaFuncSetAttribute(mixed_tc_kernel<1024, 512, 64, false>,
                         cudaFuncAttributeMaxDynamicSharedMemorySize, smem_bytes(64));

    gate_kernel<<<NB / 8, 128>>>(z, c, gw1, gb1, gw2, gb2, gw3, gb3, coef);

    // layer0: M=4096, K=4608, N=1024
    mixed_tc_kernel<512, 1024, 128, true>
        <<<dim3(1024 / 128, NB / 128), 256, smem_bytes(128)>>>(z, c, w0, b0, coef, h0);

    // layer1: M=4096, K=8704, N=1024
    mixed_tc_kernel<1024, 1024, 128, true>
        <<<dim3(1024 / 128, NB / 128), 256, smem_bytes(128)>>>(z, h0, w1, b1, coef, h1);

    // layer2: M=4096, K=8704, N=512 (BN=64 -> 256 blocks, full wave)
    mixed_tc_kernel<1024, 512, 64, false>
        <<<dim3(512 / 64, NB / 128), 256, smem_bytes(64)>>>(z, h1, w2, b2, coef, (float*)d_out);
}